// round 15
// baseline (speedup 1.0000x reference)
#include <cuda_runtime.h>
#include <cuda_fp16.h>
#include <cstdint>

// Problem constants
#define BN    131072
#define TT    12
#define HH    64
#define G3    192
#define CC    10
#define TOUT  12
#define NT    256            // 8 warps; warp = 16 seqs; CTA tile = 128 seqs
#define SEQ_PER_CTA 128
#define NITER 4              // seq-tiles per CTA (persistent staging)

// ---- SMEM byte offsets ----
// A16: fp16 h tile (carry + n-gate MMA operand), 128B pitch + XOR swizzle (R13).
// A8:  int8 h tile (rz MMA operand), 80B pitch (16-aligned; 80*r mod 128 is a
//      permutation over r=0..7 -> ldmatrix conflict-free, no swizzle) (R14).
#define OFF_A16  0                 // 128 x 128B = 16384
#define OFF_A8   16384             // 128 x 80B  = 10240
#define OFF_WE8  26624             // enc W int8 rz: 128 rows x 80B
#define OFF_WD8  36864             // dec W int8 rz
#define OFF_WE16 47104             // enc W fp16 n: 64 rows x 128B (swizzled)
#define OFF_WD16 55296             // dec W fp16 n
#define OFF_CFE  63488             // enc float coef block (840 floats)
#define OFF_CFD  66848             // dec float coef block
#define SMEM_BYTES (OFF_CFD + 840*4)
// coef float indices
#define CF_WA   0                  // w_ih feature0 [192]
#define CF_WB   192                // w_ih feature1 [192]
#define CF_BRZ  384                // b_ih+b_hh for r,z [128]
#define CF_BIHN 512                // b_ih n [64]
#define CF_BHHN 576                // b_hh n [64]
#define CF_L1W  640                // lin1 weights [64]
#define CF_L1B  704                // lin1 bias [1]
#define CF_SW   708                // per-row W scales for rz rows [128]

// device-global scratch
__device__ float g_hv[(size_t)CC * TOUT * BN * 2];   // encoder inputs (x0,x1)
__device__ float g_vals[(size_t)CC * TOUT * BN];     // decoder outputs

// ===================== helpers =====================
__device__ __forceinline__ uint32_t smem_u32_of(const void* p) {
    uint32_t a;
    asm("{ .reg .u64 t; cvta.to.shared.u64 t, %1; cvt.u32.u64 %0, t; }" : "=r"(a) : "l"(p));
    return a;
}
__device__ __forceinline__ float sigmoid_fast(float x) {
    float t, y = 0.5f * x;
    asm("tanh.approx.f32 %0, %1;" : "=f"(t) : "f"(y));
    return fmaf(0.5f, t, 0.5f);
}
__device__ __forceinline__ float tanh_fast(float x) {
    float t;
    asm("tanh.approx.f32 %0, %1;" : "=f"(t) : "f"(x));
    return t;
}

#define LDSM_X4(r0, r1, r2, r3, addr) \
    asm volatile("ldmatrix.sync.aligned.m8n8.x4.shared.b16 {%0,%1,%2,%3}, [%4];" \
                 : "=r"(r0), "=r"(r1), "=r"(r2), "=r"(r3) : "r"(addr))

// int8 IMMA: D(s32) += A(s8 16x32) * B(s8 32x8, col-major)
#define MMA16832I(dp, a0, a1, a2, a3, b0, b1) \
    asm volatile("mma.sync.aligned.m16n8k32.row.col.s32.s8.s8.s32 " \
                 "{%0,%1,%2,%3}, {%4,%5,%6,%7}, {%8,%9}, {%0,%1,%2,%3};" \
                 : "+r"((dp)[0]), "+r"((dp)[1]), "+r"((dp)[2]), "+r"((dp)[3]) \
                 : "r"(a0), "r"(a1), "r"(a2), "r"(a3), "r"(b0), "r"(b1))

// fp16-accumulate HMMA (validated R13)
#define MMA16816H(dp, a0, a1, a2, a3, b0, b1) \
    asm volatile("mma.sync.aligned.m16n8k16.row.col.f16.f16.f16.f16 " \
                 "{%0,%1}, {%2,%3,%4,%5}, {%6,%7}, {%0,%1};" \
                 : "+r"((dp)[0]), "+r"((dp)[1]) \
                 : "r"(a0), "r"(a1), "r"(a2), "r"(a3), "r"(b0), "r"(b1))

// ===================== weight staging =====================
// rz rows (0..127): int8 quant + per-row scale. n rows (128..191): fp16 swizzled.
__device__ __forceinline__ void stage_w(
    unsigned char* smem, int tid, uint32_t w8ofs, uint32_t w16ofs, uint32_t cfofs,
    const float* __restrict__ whh, const float* __restrict__ wih, int stride,
    const float* __restrict__ bih, const float* __restrict__ bhh,
    const float* __restrict__ l1w, const float* __restrict__ l1b)
{
    float* cf = (float*)(smem + cfofs);
    for (int g = tid; g < G3; g += NT) {
        const float* row = whh + g * HH;
        if (g < 128) {
            float m = 0.0f;
            #pragma unroll 8
            for (int k = 0; k < HH; ++k) m = fmaxf(m, fabsf(row[k]));
            float inv = (m > 0.0f) ? 127.0f / m : 0.0f;
            cf[CF_SW + g] = m * (1.0f / 127.0f);
            uint32_t base = w8ofs + (uint32_t)g * 80u;
            #pragma unroll
            for (int kq = 0; kq < 16; ++kq) {
                uint32_t pk = 0;
                #pragma unroll
                for (int b = 0; b < 4; ++b) {
                    int v = __float2int_rn(row[kq * 4 + b] * inv);
                    pk |= ((uint32_t)v & 0xFFu) << (8 * b);
                }
                *(uint32_t*)(smem + base + kq * 4) = pk;
            }
        } else {
            int gn = g - 128;
            #pragma unroll 8
            for (int k = 0; k < HH; ++k) {
                uint32_t off = (uint32_t)gn * 128u
                             + (uint32_t)((((k >> 3) ^ (gn & 7)) << 4) + (k & 7) * 2);
                *(__half*)(smem + w16ofs + off) = __float2half_rn(row[k]);
            }
        }
    }
    for (int t = tid; t < G3; t += NT) {
        cf[CF_WA + t] = wih[t * stride];
        cf[CF_WB + t] = (stride == 2) ? wih[t * 2 + 1] : 0.0f;
        float bi = bih[t], bh = bhh[t];
        if (t < 128) cf[CF_BRZ + t] = bi + bh;
        else { cf[CF_BIHN + t - 128] = bi; cf[CF_BHHN + t - 128] = bh; }
    }
    if (tid < HH)  cf[CF_L1W + tid] = l1w[tid];
    if (tid == HH) cf[CF_L1B] = l1b[0];
}

// ===================== one GRU step: mixed int8(rz) + fp16(n) =====================
// rz pre-activations via IMMA on A8/W8 (dequant per-row-W x per-warp-h scale);
// n pre-activations via fp16 HMMA on A16/W16 (undamped path kept at fp16 class).
// h carry lives in A16; A8 requantized from new h each step (pass 2).
template<bool HASX1, bool WANTV>
__device__ __forceinline__ void mma_step(
    unsigned char* smem, uint32_t smb, uint32_t w8ofs, uint32_t w16ofs, const float* cf,
    int warp, int group, int tg,
    int arow, int acoff, int brow8, int bcoff8, int brow16, int bcoff16, int sw7,
    float& hsc,
    float xa0, float xa1, float xb0, float xb1,
    float& va_out, float& vb_out)
{
    int Drz[64];
    #pragma unroll
    for (int i = 0; i < 64; ++i) Drz[i] = 0;
    uint32_t Dhn[16];
    #pragma unroll
    for (int i = 0; i < 16; ++i) Dhn[i] = 0u;

    __syncwarp();

    // ---- rz: int8 IMMA (validated R14 mapping) ----
    {
        const uint32_t a8_row = (uint32_t)(warp * 16 + arow) * 80u;
        const uint32_t w8b = smb + w8ofs;
        #pragma unroll
        for (int kcb = 0; kcb < 2; ++kcb) {
            uint32_t A0, A1, A2, A3;
            uint32_t aaddr = smb + OFF_A8 + a8_row + (uint32_t)((kcb * 2 + acoff) << 4);
            LDSM_X4(A0, A1, A2, A3, aaddr);
            const uint32_t bchunk = (uint32_t)((kcb * 2 + bcoff8) << 4);
            #pragma unroll
            for (int bt = 0; bt < 8; ++bt) {
                uint32_t baddr = w8b + (uint32_t)(bt * 16 + brow8) * 80u + bchunk;
                uint32_t B0, B1, B2, B3;
                LDSM_X4(B0, B1, B2, B3, baddr);
                MMA16832I(&Drz[(2 * bt) * 4],     A0, A1, A2, A3, B0, B2);
                MMA16832I(&Drz[(2 * bt + 1) * 4], A0, A1, A2, A3, B1, B3);
            }
        }
    }

    // ---- n: fp16 HMMA (validated R13 mapping) ----
    {
        const uint32_t a16_row = (uint32_t)(warp * 16 + arow) * 128u;
        const uint32_t w16b = smb + w16ofs;
        #pragma unroll
        for (int kcb = 0; kcb < 4; ++kcb) {
            const int kc = kcb * 2;
            uint32_t A0, A1, A2, A3;
            uint32_t aaddr = smb + OFF_A16 + a16_row + (uint32_t)(((kc + acoff) ^ sw7) << 4);
            LDSM_X4(A0, A1, A2, A3, aaddr);
            const uint32_t bsw = (uint32_t)(((kc + bcoff16) ^ sw7) << 4);
            const uint32_t brb = (uint32_t)brow16 * 128u + bsw;
            #pragma unroll
            for (int bt = 0; bt < 4; ++bt) {
                uint32_t baddr = w16b + (uint32_t)(bt * 16) * 128u + brb;
                uint32_t B0, B1, B2, B3;
                LDSM_X4(B0, B1, B2, B3, baddr);
                MMA16816H(&Dhn[4 * bt],     A0, A1, A2, A3, B0, B1);
                MMA16816H(&Dhn[4 * bt + 2], A0, A1, A2, A3, B2, B3);
            }
        }
    }

    __syncwarp();

    float pa = 0.0f, pb = 0.0f;
    float wm = 0.0f;

    // ---- pass 1: gates (fp32), new h -> A16, track warp |h| max ----
    #pragma unroll
    for (int t = 0; t < 8; ++t) {
        const int g2 = t * 8 + tg * 2;
        float2 war = *(const float2*)(cf + CF_WA + g2);
        float2 waz = *(const float2*)(cf + CF_WA + 64 + g2);
        float2 wan = *(const float2*)(cf + CF_WA + 128 + g2);
        float2 brr = *(const float2*)(cf + CF_BRZ + g2);
        float2 brz = *(const float2*)(cf + CF_BRZ + 64 + g2);
        float2 bin = *(const float2*)(cf + CF_BIHN + g2);
        float2 bhn = *(const float2*)(cf + CF_BHHN + g2);
        float2 swr = *(const float2*)(cf + CF_SW + g2);
        float2 swz = *(const float2*)(cf + CF_SW + 64 + g2);
        float2 wbr, wbz, wbn;
        if (HASX1) {
            wbr = *(const float2*)(cf + CF_WB + g2);
            wbz = *(const float2*)(cf + CF_WB + 64 + g2);
            wbn = *(const float2*)(cf + CF_WB + 128 + g2);
        }
        float2 l1;
        if (WANTV) l1 = *(const float2*)(cf + CF_L1W + g2);

        const float scr0 = swr.x * hsc, scr1 = swr.y * hsc;
        const float scz0 = swz.x * hsc, scz1 = swz.y * hsc;

        #pragma unroll
        for (int rh = 0; rh < 2; ++rh) {
            const float x0 = rh ? xb0 : xa0;
            const float x1 = rh ? xb1 : xa1;
            const uint32_t off16 = (uint32_t)(warp * 16 + group + rh * 8) * 128u
                                 + (uint32_t)(((t ^ group) << 4) + tg * 4);
            float2 holdf = __half22float2(*(__half2*)(smem + OFF_A16 + off16));
            float2 dn = __half22float2(*(__half2*)&Dhn[t * 2 + rh]);
            float hn[2];
            #pragma unroll
            for (int u = 0; u < 2; ++u) {
                float pr = (float)Drz[t * 4 + rh * 2 + u]       * (u ? scr1 : scr0)
                         + (u ? brr.y : brr.x) + (u ? war.y : war.x) * x0;
                float pz = (float)Drz[(t + 8) * 4 + rh * 2 + u] * (u ? scz1 : scz0)
                         + (u ? brz.y : brz.x) + (u ? waz.y : waz.x) * x0;
                float pn = (u ? dn.y : dn.x) + (u ? bhn.y : bhn.x);
                float gx = (u ? bin.y : bin.x) + (u ? wan.y : wan.x) * x0;
                if (HASX1) {
                    pr = fmaf((u ? wbr.y : wbr.x), x1, pr);
                    pz = fmaf((u ? wbz.y : wbz.x), x1, pz);
                    gx = fmaf((u ? wbn.y : wbn.x), x1, gx);
                }
                float rr = sigmoid_fast(pr);
                float zz = sigmoid_fast(pz);
                float nn = tanh_fast(fmaf(rr, pn, gx));
                float hold = u ? holdf.y : holdf.x;
                hn[u] = nn + zz * (hold - nn);
            }
            *(__half2*)(smem + OFF_A16 + off16) = __floats2half2_rn(hn[0], hn[1]);
            wm = fmaxf(wm, fmaxf(fabsf(hn[0]), fabsf(hn[1])));
            if (WANTV) {
                float d = fmaf(hn[0], l1.x, hn[1] * l1.y);
                if (rh == 0) pa += d; else pb += d;
            }
        }
    }

    // warp-wide |h| max -> new h scale
    #pragma unroll
    for (int s = 16; s > 0; s >>= 1)
        wm = fmaxf(wm, __shfl_xor_sync(0xffffffff, wm, s));
    const float qinv = 127.0f / fmaxf(wm, 1e-30f);
    hsc = wm * (1.0f / 127.0f);

    // ---- pass 2: requantize h (from A16) -> A8 ----
    const uint32_t arow_a8 = (uint32_t)(warp * 16 + group) * 80u;
    #pragma unroll
    for (int t = 0; t < 8; ++t) {
        #pragma unroll
        for (int rh = 0; rh < 2; ++rh) {
            const uint32_t off16 = (uint32_t)(warp * 16 + group + rh * 8) * 128u
                                 + (uint32_t)(((t ^ group) << 4) + tg * 4);
            float2 f = __half22float2(*(__half2*)(smem + OFF_A16 + off16));
            int ia = __float2int_rn(f.x * qinv);
            int ib = __float2int_rn(f.y * qinv);
            uint16_t pk = (uint16_t)((ia & 0xFF) | ((ib & 0xFF) << 8));
            const uint32_t aoff = arow_a8 + (rh ? 8u * 80u : 0u) + (uint32_t)(t * 8 + tg * 2);
            *(uint16_t*)(smem + OFF_A8 + aoff) = pk;
        }
    }

    if (WANTV) { va_out = pa; vb_out = pb; }
}

// ===================== main kernel =====================
__global__ void __launch_bounds__(NT, 2) krnn_mma(
    const float* __restrict__ X,
    const float* __restrict__ enc_w_ih, const float* __restrict__ enc_w_hh,
    const float* __restrict__ enc_b_ih, const float* __restrict__ enc_b_hh,
    const float* __restrict__ dec_w_ih, const float* __restrict__ dec_w_hh,
    const float* __restrict__ dec_b_ih, const float* __restrict__ dec_b_hh,
    const float* __restrict__ lin1_w,   const float* __restrict__ lin1_b)
{
    extern __shared__ unsigned char smem[];
    const int tid   = threadIdx.x;
    const int l     = tid & 31;
    const int warp  = tid >> 5;
    const int c     = (CC - 1) - blockIdx.y;          // longest-first
    const uint32_t smb = smem_u32_of(smem);

    const int group  = l >> 2;
    const int tg     = l & 3;
    const int arow   = (l & 7) + ((l >> 3) & 1) * 8;
    const int acoff  = (l >> 4) & 1;
    const int brow8  = (l & 7) + ((l >> 3) & 1) * 8;  // int8 B map (R14)
    const int bcoff8 = (l >> 4) & 1;
    const int brow16 = (l & 7) + ((l >> 4) & 1) * 8;  // fp16 B map (R13)
    const int bcoff16 = (l >> 3) & 1;
    const int sw7    = l & 7;

    // stage BOTH weight sets once per CTA
    stage_w(smem, tid, OFF_WE8, OFF_WE16, OFF_CFE,
            enc_w_hh + c * (G3 * HH), enc_w_ih + c * (G3 * 2), 2,
            enc_b_ih + c * G3, enc_b_hh + c * G3, lin1_w + c * HH, lin1_b + c);
    stage_w(smem, tid, OFF_WD8, OFF_WD16, OFF_CFD,
            dec_w_hh + c * (G3 * HH), dec_w_ih + c * G3, 1,
            dec_b_ih + c * G3, dec_b_hh + c * G3, lin1_w + c * HH, lin1_b + c);
    __syncthreads();          // the ONLY block-wide barrier

    const float* cfe = (const float*)(smem + OFF_CFE);
    const float* cfd = (const float*)(smem + OFF_CFD);
    const float  l1b = cfd[CF_L1B];
    const int    s_enc = c + 3;
    const float2* hvc = (const float2*)g_hv + (size_t)c * TOUT * BN;
    float vdum0, vdum1;

    #pragma unroll 1
    for (int tile = 0; tile < NITER; ++tile) {
        const int seq_a = (blockIdx.x * NITER + tile) * SEQ_PER_CTA + warp * 16 + group;
        const int seq_b = seq_a + 8;

        // zero this warp's private A16 + A8 bands (h = 0)
        {
            uint4 z4; z4.x = z4.y = z4.z = z4.w = 0u;
            const uint32_t a16b = (uint32_t)warp * 2048u;
            #pragma unroll
            for (int i = 0; i < 4; ++i)
                *(uint4*)(smem + OFF_A16 + a16b + (uint32_t)(l * 16 + i * 512)) = z4;
            const uint32_t a8b = (uint32_t)warp * 1280u;
            #pragma unroll
            for (int i = 0; i < 10; ++i)
                *(uint32_t*)(smem + OFF_A8 + a8b + (uint32_t)(l * 4 + i * 128)) = 0u;
        }
        float hsc = 0.0f;     // h==0 -> Drz==0; scale value irrelevant

        // ---- encoder ----
        #pragma unroll 1
        for (int st = 0; st < s_enc; ++st) {
            float2 xa = hvc[(size_t)st * BN + seq_a];
            float2 xb = hvc[(size_t)st * BN + seq_b];
            mma_step<true, false>(smem, smb, OFF_WE8, OFF_WE16, cfe, warp, group, tg,
                                  arow, acoff, brow8, bcoff8, brow16, bcoff16, sw7, hsc,
                                  xa.x, xa.y, xb.x, xb.y, vdum0, vdum1);
        }

        // ---- decoder ----
        float va = X[(size_t)seq_a * (TT * 2) + 22];      // X[seq, t=11, f=0]
        float vb = X[(size_t)seq_b * (TT * 2) + 22];
        #pragma unroll 1
        for (int st = 0; st < TOUT; ++st) {
            float pa, pb;
            mma_step<false, true>(smem, smb, OFF_WD8, OFF_WD16, cfd, warp, group, tg,
                                  arow, acoff, brow8, bcoff8, brow16, bcoff16, sw7, hsc,
                                  va, 0.0f, vb, 0.0f, pa, pb);
            pa += __shfl_xor_sync(0xffffffff, pa, 1);
            pa += __shfl_xor_sync(0xffffffff, pa, 2);
            pb += __shfl_xor_sync(0xffffffff, pb, 1);
            pb += __shfl_xor_sync(0xffffffff, pb, 2);
            va = pa + l1b;
            vb = pb + l1b;
            if (tg == 0) {
                g_vals[(size_t)(c * TOUT + st) * BN + seq_a] = va;
                g_vals[(size_t)(c * TOUT + st) * BN + seq_b] = vb;
            }
        }
    }
}

// ===================== hv precompute =====================
__global__ void __launch_bounds__(256) krnn_hv(
    const float* __restrict__ X,
    const float* __restrict__ lin2_w, const float* __restrict__ lin2_b)
{
    const int seq = blockIdx.x * 256 + threadIdx.x;
    float Xl[24];
    {
        const float4* xp = (const float4*)(X + (size_t)seq * (TT * 2));
        #pragma unroll
        for (int q = 0; q < 6; ++q) {
            float4 v = xp[q];
            Xl[4*q+0] = v.x; Xl[4*q+1] = v.y; Xl[4*q+2] = v.z; Xl[4*q+3] = v.w;
        }
    }
    float2* hvp = (float2*)g_hv;
    for (int c = 0; c < CC; ++c) {
        const int s = c + 3;
        for (int st = 0; st < s; ++st) {
            float b = lin2_b[c * 12 + st];
            float x0 = b, x1 = b;
            #pragma unroll
            for (int t = 0; t < TT; ++t) {
                float w = lin2_w[c * 144 + st * 12 + t];
                x0 = fmaf(Xl[2 * t],     w, x0);
                x1 = fmaf(Xl[2 * t + 1], w, x1);
            }
            hvp[(size_t)(c * TOUT + st) * BN + seq] = make_float2(x0, x1);
        }
    }
}

// ===================== final combine =====================
__global__ void __launch_bounds__(256) krnn_combine(
    const float* __restrict__ X,
    const float* __restrict__ embed1,
    float* __restrict__ out)
{
    const int seq = blockIdx.x * 256 + threadIdx.x;

    float q[TT];
    #pragma unroll
    for (int t = 0; t < TT; ++t) q[t] = X[(size_t)seq * (TT * 2) + t * 2];

    float wq[TOUT];
    #pragma unroll
    for (int o = 0; o < TOUT; ++o) {
        float a = 0.0f;
        #pragma unroll
        for (int t = 0; t < TT; ++t) a = fmaf(q[t], embed1[t * TOUT + o], a);
        wq[o] = a;
    }

    float ov[TOUT * CC];
    #pragma unroll
    for (int cc = 0; cc < CC; ++cc)
        #pragma unroll
        for (int o = 0; o < TOUT; ++o)
            ov[o * CC + cc] = g_vals[((size_t)cc * TOUT + o) * BN + seq];

    float wc[CC];
    #pragma unroll
    for (int cc = 0; cc < CC; ++cc) {
        float a = 0.0f;
        #pragma unroll
        for (int o = 0; o < TOUT; ++o) a = fmaf(wq[o], ov[o * CC + cc], a);
        wc[cc] = a;
    }

    float m = wc[0];
    #pragma unroll
    for (int cc = 1; cc < CC; ++cc) m = fmaxf(m, wc[cc]);
    float e[CC]; float ssum = 0.0f;
    #pragma unroll
    for (int cc = 0; cc < CC; ++cc) { e[cc] = expf(wc[cc] - m); ssum += e[cc]; }
    float inv = 1.0f / ssum;

    #pragma unroll
    for (int o = 0; o < TOUT; ++o) {
        float a = 0.0f;
        #pragma unroll
        for (int cc = 0; cc < CC; ++cc) a = fmaf(ov[o * CC + cc], e[cc], a);
        out[(size_t)seq * TOUT + o] = a * inv;
    }
}

extern "C" void kernel_launch(void* const* d_in, const int* in_sizes, int n_in,
                              void* d_out, int out_size)
{
    const float* X        = (const float*)d_in[1];
    const float* enc_w_ih = (const float*)d_in[2];
    const float* enc_w_hh = (const float*)d_in[3];
    const float* enc_b_ih = (const float*)d_in[4];
    const float* enc_b_hh = (const float*)d_in[5];
    const float* dec_w_ih = (const float*)d_in[6];
    const float* dec_w_hh = (const float*)d_in[7];
    const float* dec_b_ih = (const float*)d_in[8];
    const float* dec_b_hh = (const float*)d_in[9];
    const float* lin1_w   = (const float*)d_in[10];
    const float* lin1_b   = (const float*)d_in[11];
    const float* lin2_w   = (const float*)d_in[12];
    const float* lin2_b   = (const float*)d_in[13];
    const float* embed1   = (const float*)d_in[14];

    cudaFuncSetAttribute(krnn_mma, cudaFuncAttributeMaxDynamicSharedMemorySize, SMEM_BYTES);

    krnn_hv<<<BN / 256, 256>>>(X, lin2_w, lin2_b);

    dim3 grid(BN / (SEQ_PER_CTA * NITER), CC);
    krnn_mma<<<grid, NT, SMEM_BYTES>>>(
        X, enc_w_ih, enc_w_hh, enc_b_ih, enc_b_hh,
        dec_w_ih, dec_w_hh, dec_b_ih, dec_b_hh,
        lin1_w, lin1_b);

    krnn_combine<<<BN / 256, 256>>>(X, embed1, (float*)d_out);
}

// round 16
// speedup vs baseline: 2.2300x; 2.2300x over previous
#include <cuda_runtime.h>
#include <cuda_fp16.h>
#include <cstdint>

// Problem constants
#define BN    131072
#define TT    12
#define HH    64
#define G3    192
#define CC    10
#define TOUT  12
#define NT    256            // 8 warps; warp = 16 seqs; CTA tile = 128 seqs
#define SEQ_PER_CTA 128
#define NITER 4              // seq-tiles per CTA (persistent staging)

// ---- SMEM byte offsets ----
#define OFF_A    0                 // h fp16: 128 rows x 128B, swizzled (per-warp-private bands)
#define OFF_WE   16384             // enc W fp16: 192 rows x 128B, swizzled
#define OFF_WD   40960             // dec W fp16
#define OFF_CFE  65536             // enc float coef block (708 floats)
#define OFF_CFD  68368             // dec float coef block (708 floats)
#define OFF_HCE  71200             // enc half coef block (640 halves)
#define OFF_HCD  72480             // dec half coef block
#define SMEM_BYTES (OFF_HCD + 640*2)
// float coef indices
#define CF_L1W  640                // lin1 weights [64]
#define CF_L1B  704                // lin1 bias [1]
// half coef indices
#define HF_WA   0                  // w_ih feature0 [192]
#define HF_WB   192                // w_ih feature1 [192]
#define HF_BRZ  384                // b_ih+b_hh for r,z [128]
#define HF_BIN  512                // b_ih n [64]
#define HF_BHN  576                // b_hh n [64]

// device-global scratch
__device__ float g_hv[(size_t)CC * TOUT * BN * 2];   // encoder inputs (x0,x1)
__device__ float g_vals[(size_t)CC * TOUT * BN];     // decoder outputs

// ===================== helpers =====================
__device__ __forceinline__ uint32_t smem_u32_of(const void* p) {
    uint32_t a;
    asm("{ .reg .u64 t; cvta.to.shared.u64 t, %1; cvt.u32.u64 %0, t; }" : "=r"(a) : "l"(p));
    return a;
}
__device__ __forceinline__ __half2 tanh2(__half2 x) {
    uint32_t d, s = *(uint32_t*)&x;
    asm("tanh.approx.f16x2 %0, %1;" : "=r"(d) : "r"(s));
    return *(__half2*)&d;
}
// sigmoid2(x) = 0.5 + 0.5*tanh(0.5x)
__device__ __forceinline__ __half2 sigmoid2(__half2 x, __half2 h05) {
    return __hfma2(tanh2(__hmul2(x, h05)), h05, h05);
}

#define LDSM_X4(r0, r1, r2, r3, addr) \
    asm volatile("ldmatrix.sync.aligned.m8n8.x4.shared.b16 {%0,%1,%2,%3}, [%4];" \
                 : "=r"(r0), "=r"(r1), "=r"(r2), "=r"(r3) : "r"(addr))

// fp16-accumulate HMMA (validated R13)
#define MMA16816H(dp, a0, a1, a2, a3, b0, b1) \
    asm volatile("mma.sync.aligned.m16n8k16.row.col.f16.f16.f16.f16 " \
                 "{%0,%1}, {%2,%3,%4,%5}, {%6,%7}, {%0,%1};" \
                 : "+r"((dp)[0]), "+r"((dp)[1]) \
                 : "r"(a0), "r"(a1), "r"(a2), "r"(a3), "r"(b0), "r"(b1))

// ===================== weight staging =====================
__device__ __forceinline__ void stage_w(
    unsigned char* smem, int tid, uint32_t wofs, uint32_t cfofs, uint32_t hcofs,
    const float* __restrict__ whh, const float* __restrict__ wih, int stride,
    const float* __restrict__ bih, const float* __restrict__ bhh,
    const float* __restrict__ l1w, const float* __restrict__ l1b)
{
    for (int idx = tid; idx < G3 * HH; idx += NT) {
        int g = idx >> 6, k = idx & 63;
        __half hi = __float2half_rn(whh[idx]);
        uint32_t off = (uint32_t)g * 128u + (uint32_t)((((k >> 3) ^ (g & 7)) << 4) + (k & 7) * 2);
        *(__half*)(smem + wofs + off) = hi;
    }
    float* cf = (float*)(smem + cfofs);
    __half* hc = (__half*)(smem + hcofs);
    for (int t = tid; t < G3; t += NT) {
        hc[HF_WA + t] = __float2half_rn(wih[t * stride]);
        hc[HF_WB + t] = __float2half_rn((stride == 2) ? wih[t * 2 + 1] : 0.0f);
        float bi = bih[t], bh = bhh[t];
        if (t < 128) hc[HF_BRZ + t] = __float2half_rn(bi + bh);
        else { hc[HF_BIN + t - 128] = __float2half_rn(bi); hc[HF_BHN + t - 128] = __float2half_rn(bh); }
    }
    if (tid < HH)  cf[CF_L1W + tid] = l1w[tid];
    if (tid == HH) cf[CF_L1B] = l1b[0];
}

// ===================== one GRU step (HMMA fp16-acc, half2 epilogue) ============
// D (fp16 accum) = W·h; Dh[T*2+rh] is f16x2 (u0,u1) pair — native half2 lanes.
// Entire epilogue in f16x2: HFMA2 gate math + tanh.approx.f16x2 activations.
// h carry in smem A tile (per-warp-private rows -> __syncwarp only).
template<bool HASX1, bool WANTV>
__device__ __forceinline__ void mma_step(
    unsigned char* smem, uint32_t smb, uint32_t wofs, const __half* hc, const float* cf,
    int warp, int group, int tg,
    int arow, int acoff, int brow, int bcoff, int sw7,
    float xa0, float xa1, float xb0, float xb1,
    float& va_out, float& vb_out)
{
    uint32_t Dh[48];
    #pragma unroll
    for (int i = 0; i < 48; ++i) Dh[i] = 0u;

    __syncwarp();

    const uint32_t a_row_b = (uint32_t)(warp * 16 + arow) * 128u;
    const uint32_t wbase = smb + wofs;

    #pragma unroll 1
    for (int kcb = 0; kcb < 4; ++kcb) {
        const int kc = kcb * 2;

        uint32_t A0, A1, A2, A3;
        uint32_t aaddr = smb + OFF_A + a_row_b + (uint32_t)(((kc + acoff) ^ sw7) << 4);
        LDSM_X4(A0, A1, A2, A3, aaddr);

        const uint32_t bsw = (uint32_t)(((kc + bcoff) ^ sw7) << 4);
        const uint32_t brb = (uint32_t)brow * 128u + bsw;
        #pragma unroll
        for (int bt = 0; bt < 12; ++bt) {
            const uint32_t brow_off = (uint32_t)(bt * 16) * 128u + brb;
            uint32_t B0, B1, B2, B3;
            LDSM_X4(B0, B1, B2, B3, wbase + brow_off);
            MMA16816H(&Dh[4 * bt],     A0, A1, A2, A3, B0, B1);
            MMA16816H(&Dh[4 * bt + 2], A0, A1, A2, A3, B2, B3);
        }
    }

    __syncwarp();

    float pa = 0.0f, pb = 0.0f;
    const __half2 h05 = __float2half2_rn(0.5f);
    const __half2 xa0h = __float2half2_rn(xa0);
    const __half2 xb0h = __float2half2_rn(xb0);
    __half2 xa1h, xb1h;
    if (HASX1) { xa1h = __float2half2_rn(xa1); xb1h = __float2half2_rn(xb1); }

    // ---- epilogue: half2 gates, h update, half2 store ----
    #pragma unroll
    for (int t = 0; t < 8; ++t) {
        const int g2 = t * 8 + tg * 2;
        __half2 war = *(const __half2*)(hc + HF_WA + g2);
        __half2 waz = *(const __half2*)(hc + HF_WA + 64 + g2);
        __half2 wan = *(const __half2*)(hc + HF_WA + 128 + g2);
        __half2 brr = *(const __half2*)(hc + HF_BRZ + g2);
        __half2 brz = *(const __half2*)(hc + HF_BRZ + 64 + g2);
        __half2 bin = *(const __half2*)(hc + HF_BIN + g2);
        __half2 bhn = *(const __half2*)(hc + HF_BHN + g2);
        __half2 wbr, wbz, wbn;
        if (HASX1) {
            wbr = *(const __half2*)(hc + HF_WB + g2);
            wbz = *(const __half2*)(hc + HF_WB + 64 + g2);
            wbn = *(const __half2*)(hc + HF_WB + 128 + g2);
        }
        float2 l1;
        if (WANTV) l1 = *(const float2*)(cf + CF_L1W + g2);

        #pragma unroll
        for (int rh = 0; rh < 2; ++rh) {
            const __half2 x0h = rh ? xb0h : xa0h;
            const uint32_t off = (uint32_t)(warp * 16 + group + rh * 8) * 128u
                               + (uint32_t)(((t ^ group) << 4) + tg * 4);
            __half2 hold2 = *(__half2*)(smem + OFF_A + off);

            __half2 pr = __hfma2(war, x0h, __hadd2(*(__half2*)&Dh[t * 2 + rh], brr));
            __half2 pz = __hfma2(waz, x0h, __hadd2(*(__half2*)&Dh[(t + 8) * 2 + rh], brz));
            __half2 pn = __hadd2(*(__half2*)&Dh[(t + 16) * 2 + rh], bhn);
            __half2 gx = __hfma2(wan, x0h, bin);
            if (HASX1) {
                const __half2 x1h = rh ? xb1h : xa1h;
                pr = __hfma2(wbr, x1h, pr);
                pz = __hfma2(wbz, x1h, pz);
                gx = __hfma2(wbn, x1h, gx);
            }
            __half2 rr = sigmoid2(pr, h05);
            __half2 zz = sigmoid2(pz, h05);
            __half2 nn = tanh2(__hfma2(rr, pn, gx));
            __half2 h2 = __hfma2(zz, __hsub2(hold2, nn), nn);
            *(__half2*)(smem + OFF_A + off) = h2;
            if (WANTV) {
                float2 hf = __half22float2(h2);
                float d = fmaf(hf.x, l1.x, hf.y * l1.y);
                if (rh == 0) pa += d; else pb += d;
            }
        }
    }
    if (WANTV) { va_out = pa; vb_out = pb; }
}

// ===================== main kernel =====================
__global__ void __launch_bounds__(NT, 2) krnn_mma(
    const float* __restrict__ X,
    const float* __restrict__ enc_w_ih, const float* __restrict__ enc_w_hh,
    const float* __restrict__ enc_b_ih, const float* __restrict__ enc_b_hh,
    const float* __restrict__ dec_w_ih, const float* __restrict__ dec_w_hh,
    const float* __restrict__ dec_b_ih, const float* __restrict__ dec_b_hh,
    const float* __restrict__ lin1_w,   const float* __restrict__ lin1_b)
{
    extern __shared__ unsigned char smem[];
    const int tid   = threadIdx.x;
    const int l     = tid & 31;
    const int warp  = tid >> 5;
    const int c     = (CC - 1) - blockIdx.y;          // longest-first
    const uint32_t smb = smem_u32_of(smem);

    const int group = l >> 2;
    const int tg    = l & 3;
    const int arow  = (l & 7) + ((l >> 3) & 1) * 8;
    const int acoff = (l >> 4) & 1;
    const int brow  = (l & 7) + ((l >> 4) & 1) * 8;
    const int bcoff = (l >> 3) & 1;
    const int sw7   = l & 7;

    // stage BOTH weight sets once per CTA
    stage_w(smem, tid, OFF_WE, OFF_CFE, OFF_HCE,
            enc_w_hh + c * (G3 * HH), enc_w_ih + c * (G3 * 2), 2,
            enc_b_ih + c * G3, enc_b_hh + c * G3, lin1_w + c * HH, lin1_b + c);
    stage_w(smem, tid, OFF_WD, OFF_CFD, OFF_HCD,
            dec_w_hh + c * (G3 * HH), dec_w_ih + c * G3, 1,
            dec_b_ih + c * G3, dec_b_hh + c * G3, lin1_w + c * HH, lin1_b + c);
    __syncthreads();          // the ONLY block-wide barrier

    const float*  cfe = (const float*)(smem + OFF_CFE);
    const float*  cfd = (const float*)(smem + OFF_CFD);
    const __half* hce = (const __half*)(smem + OFF_HCE);
    const __half* hcd = (const __half*)(smem + OFF_HCD);
    const float   l1b = cfd[CF_L1B];
    const int     s_enc = c + 3;
    const float2* hvc = (const float2*)g_hv + (size_t)c * TOUT * BN;
    float vdum0, vdum1;

    #pragma unroll 1
    for (int tile = 0; tile < NITER; ++tile) {
        const int seq_a = (blockIdx.x * NITER + tile) * SEQ_PER_CTA + warp * 16 + group;
        const int seq_b = seq_a + 8;

        // zero this warp's private A rows (h = 0); mma_step's syncwarp orders it
        {
            uint4 z; z.x = z.y = z.z = z.w = 0u;
            const uint32_t abase = (uint32_t)warp * 2048u;
            #pragma unroll
            for (int i = 0; i < 4; ++i)
                *(uint4*)(smem + OFF_A + abase + (uint32_t)(l * 16 + i * 512)) = z;
        }

        // ---- encoder ----
        #pragma unroll 1
        for (int st = 0; st < s_enc; ++st) {
            float2 xa = hvc[(size_t)st * BN + seq_a];
            float2 xb = hvc[(size_t)st * BN + seq_b];
            mma_step<true, false>(smem, smb, OFF_WE, hce, cfe, warp, group, tg,
                                  arow, acoff, brow, bcoff, sw7,
                                  xa.x, xa.y, xb.x, xb.y, vdum0, vdum1);
        }

        // ---- decoder ----
        float va = X[(size_t)seq_a * (TT * 2) + 22];      // X[seq, t=11, f=0]
        float vb = X[(size_t)seq_b * (TT * 2) + 22];
        #pragma unroll 1
        for (int st = 0; st < TOUT; ++st) {
            float pa, pb;
            mma_step<false, true>(smem, smb, OFF_WD, hcd, cfd, warp, group, tg,
                                  arow, acoff, brow, bcoff, sw7,
                                  va, 0.0f, vb, 0.0f, pa, pb);
            pa += __shfl_xor_sync(0xffffffff, pa, 1);
            pa += __shfl_xor_sync(0xffffffff, pa, 2);
            pb += __shfl_xor_sync(0xffffffff, pb, 1);
            pb += __shfl_xor_sync(0xffffffff, pb, 2);
            va = pa + l1b;
            vb = pb + l1b;
            if (tg == 0) {
                g_vals[(size_t)(c * TOUT + st) * BN + seq_a] = va;
                g_vals[(size_t)(c * TOUT + st) * BN + seq_b] = vb;
            }
        }
    }
}

// ===================== hv precompute =====================
__global__ void __launch_bounds__(256) krnn_hv(
    const float* __restrict__ X,
    const float* __restrict__ lin2_w, const float* __restrict__ lin2_b)
{
    const int seq = blockIdx.x * 256 + threadIdx.x;
    float Xl[24];
    {
        const float4* xp = (const float4*)(X + (size_t)seq * (TT * 2));
        #pragma unroll
        for (int q = 0; q < 6; ++q) {
            float4 v = xp[q];
            Xl[4*q+0] = v.x; Xl[4*q+1] = v.y; Xl[4*q+2] = v.z; Xl[4*q+3] = v.w;
        }
    }
    float2* hvp = (float2*)g_hv;
    for (int c = 0; c < CC; ++c) {
        const int s = c + 3;
        for (int st = 0; st < s; ++st) {
            float b = lin2_b[c * 12 + st];
            float x0 = b, x1 = b;
            #pragma unroll
            for (int t = 0; t < TT; ++t) {
                float w = lin2_w[c * 144 + st * 12 + t];
                x0 = fmaf(Xl[2 * t],     w, x0);
                x1 = fmaf(Xl[2 * t + 1], w, x1);
            }
            hvp[(size_t)(c * TOUT + st) * BN + seq] = make_float2(x0, x1);
        }
    }
}

// ===================== final combine =====================
__global__ void __launch_bounds__(256) krnn_combine(
    const float* __restrict__ X,
    const float* __restrict__ embed1,
    float* __restrict__ out)
{
    const int seq = blockIdx.x * 256 + threadIdx.x;

    float q[TT];
    #pragma unroll
    for (int t = 0; t < TT; ++t) q[t] = X[(size_t)seq * (TT * 2) + t * 2];

    float wq[TOUT];
    #pragma unroll
    for (int o = 0; o < TOUT; ++o) {
        float a = 0.0f;
        #pragma unroll
        for (int t = 0; t < TT; ++t) a = fmaf(q[t], embed1[t * TOUT + o], a);
        wq[o] = a;
    }

    float ov[TOUT * CC];
    #pragma unroll
    for (int cc = 0; cc < CC; ++cc)
        #pragma unroll
        for (int o = 0; o < TOUT; ++o)
            ov[o * CC + cc] = g_vals[((size_t)cc * TOUT + o) * BN + seq];

    float wc[CC];
    #pragma unroll
    for (int cc = 0; cc < CC; ++cc) {
        float a = 0.0f;
        #pragma unroll
        for (int o = 0; o < TOUT; ++o) a = fmaf(wq[o], ov[o * CC + cc], a);
        wc[cc] = a;
    }

    float m = wc[0];
    #pragma unroll
    for (int cc = 1; cc < CC; ++cc) m = fmaxf(m, wc[cc]);
    float e[CC]; float ssum = 0.0f;
    #pragma unroll
    for (int cc = 0; cc < CC; ++cc) { e[cc] = expf(wc[cc] - m); ssum += e[cc]; }
    float inv = 1.0f / ssum;

    #pragma unroll
    for (int o = 0; o < TOUT; ++o) {
        float a = 0.0f;
        #pragma unroll
        for (int cc = 0; cc < CC; ++cc) a = fmaf(ov[o * CC + cc], e[cc], a);
        out[(size_t)seq * TOUT + o] = a * inv;
    }
}

extern "C" void kernel_launch(void* const* d_in, const int* in_sizes, int n_in,
                              void* d_out, int out_size)
{
    const float* X        = (const float*)d_in[1];
    const float* enc_w_ih = (const float*)d_in[2];
    const float* enc_w_hh = (const float*)d_in[3];
    const float* enc_b_ih = (const float*)d_in[4];
    const float* enc_b_hh = (const float*)d_in[5];
    const float* dec_w_ih = (const float*)d_in[6];
    const float* dec_w_hh = (const float*)d_in[7];
    const float* dec_b_ih = (const float*)d_in[8];
    const float* dec_b_hh = (const float*)d_in[9];
    const float* lin1_w   = (const float*)d_in[10];
    const float* lin1_b   = (const float*)d_in[11];
    const float* lin2_w   = (const float*)d_in[12];
    const float* lin2_b   = (const float*)d_in[13];
    const float* embed1   = (const float*)d_in[14];

    cudaFuncSetAttribute(krnn_mma, cudaFuncAttributeMaxDynamicSharedMemorySize, SMEM_BYTES);

    krnn_hv<<<BN / 256, 256>>>(X, lin2_w, lin2_b);

    dim3 grid(BN / (SEQ_PER_CTA * NITER), CC);
    krnn_mma<<<grid, NT, SMEM_BYTES>>>(
        X, enc_w_ih, enc_w_hh, enc_b_ih, enc_b_hh,
        dec_w_ih, dec_w_hh, dec_b_ih, dec_b_hh,
        lin1_w, lin1_b);

    krnn_combine<<<BN / 256, 256>>>(X, embed1, (float*)d_out);
}